// round 1
// baseline (speedup 1.0000x reference)
#include <cuda_runtime.h>
#include <math.h>

#define B_   16384
#define KDIM 3072

// ---------------- gate descriptor table ----------------
// type: 0=U3(wire a), 1=ZZ(a,b), 2=YY, 3=XX, 4=CU3(ctrl=a,tgt=b), 5=ARB(pauli w0 on a, w1 on b)
// src: 0=conv(480? ->240 floats), 1=pool(24), 2=last(15); off = float offset
typedef struct { int type, a, b, src, off, w0, w1; } GateDesc;

__constant__ GateDesc g_desc[66] = {
  // layer0 pair(0,2)
  {0,0,0,0,0,0,0},{0,2,0,0,33,0,0},{1,0,2,0,6,0,0},{2,0,2,0,7,0,0},{3,0,2,0,8,0,0},{0,0,0,0,9,0,0},{0,2,0,0,42,0,0},
  // pair(1,3)
  {0,1,0,0,15,0,0},{0,3,0,0,48,0,0},{1,1,3,0,21,0,0},{2,1,3,0,22,0,0},{3,1,3,0,23,0,0},{0,1,0,0,24,0,0},{0,3,0,0,57,0,0},
  // pair(4,6)
  {0,4,0,0,60,0,0},{0,6,0,0,93,0,0},{1,4,6,0,66,0,0},{2,4,6,0,67,0,0},{3,4,6,0,68,0,0},{0,4,0,0,69,0,0},{0,6,0,0,102,0,0},
  // pair(5,7)
  {0,5,0,0,75,0,0},{0,7,0,0,108,0,0},{1,5,7,0,81,0,0},{2,5,7,0,82,0,0},{3,5,7,0,83,0,0},{0,5,0,0,84,0,0},{0,7,0,0,117,0,0},
  // pool0: cu3 ctrl,tgt
  {4,1,0,1,0,0,0},{4,3,2,1,3,0,0},{4,5,4,1,6,0,0},{4,7,6,1,9,0,0},
  // layer1 pair(0,2), conv base 120
  {0,0,0,0,120,0,0},{0,2,0,0,153,0,0},{1,0,2,0,126,0,0},{2,0,2,0,127,0,0},{3,0,2,0,128,0,0},{0,0,0,0,129,0,0},{0,2,0,0,162,0,0},
  // singles q4
  {0,4,0,0,180,0,0},{0,4,0,0,183,0,0},{0,4,0,0,186,0,0},{0,4,0,0,189,0,0},{0,4,0,0,192,0,0},
  // singles q6
  {0,6,0,0,210,0,0},{0,6,0,0,213,0,0},{0,6,0,0,216,0,0},{0,6,0,0,219,0,0},{0,6,0,0,222,0,0},
  // pool1
  {4,2,0,1,12,0,0},{4,6,4,1,15,0,0},
  // arbitrary_unitary on (0,4): gray pauli words (cw0 -> qubit0, cw1 -> qubit4)
  {5,0,4,2,0,1,0},{5,0,4,2,1,2,0},{5,0,4,2,2,3,0},{5,0,4,2,3,3,1},{5,0,4,2,4,0,1},
  {5,0,4,2,5,1,1},{5,0,4,2,6,2,1},{5,0,4,2,7,2,2},{5,0,4,2,8,3,2},{5,0,4,2,9,0,2},
  {5,0,4,2,10,1,2},{5,0,4,2,11,1,3},{5,0,4,2,12,2,3},{5,0,4,2,13,3,3},{5,0,4,2,14,0,3}
};

// Pauli 2x2 complex tables: I, X, Y, Z ; PT[p][row*2+col]
__constant__ float2 PT[4][4] = {
  {{1.f,0.f},{0.f,0.f},{0.f,0.f},{1.f,0.f}},
  {{0.f,0.f},{1.f,0.f},{1.f,0.f},{0.f,0.f}},
  {{0.f,0.f},{0.f,-1.f},{0.f,1.f},{0.f,0.f}},
  {{1.f,0.f},{0.f,0.f},{0.f,0.f},{-1.f,0.f}}
};

// ---------------- device scratch (no allocations allowed) ----------------
__device__ float2 d_G[66*16];      // gate matrices
__device__ float2 d_U[256*256];    // U[k*256 + col]
__device__ float  d_M[256*256];    // A = Re(U^dag Z0 U)
__device__ float4 d_mpad[2187];    // 6561 Pauli coeffs, groups of 3 padded to float4
__device__ float  d_red[B_*8];     // tanh(x@W^T+b)
__device__ float  d_part[3*B_];    // partial contractions per slice

__device__ __forceinline__ float2 cm(float2 a, float2 b){
    return make_float2(a.x*b.x - a.y*b.y, a.x*b.y + a.y*b.x);
}
__device__ __forceinline__ float2 ca(float2 a, float2 b){
    return make_float2(a.x+b.x, a.y+b.y);
}

// ---------------- 1. build gate matrices (1 tiny block) ----------------
__global__ void k_gates(const float* __restrict__ conv, const float* __restrict__ pool,
                        const float* __restrict__ last) {
    int g = threadIdx.x;
    if (g >= 66) return;
    GateDesc d = g_desc[g];
    const float* src = (d.src==0) ? conv : ((d.src==1) ? pool : last);
    float2 M[16];
    #pragma unroll
    for (int i=0;i<16;i++) M[i]=make_float2(0.f,0.f);

    if (d.type==0 || d.type==4) {
        float th=src[d.off], ph=src[d.off+1], lam=src[d.off+2];
        float s,c;   sincosf(0.5f*th,&s,&c);
        float sl,cl; sincosf(lam,&sl,&cl);
        float sp,cp; sincosf(ph,&sp,&cp);
        float spl,cpl; sincosf(ph+lam,&spl,&cpl);
        float2 u00=make_float2(c,0.f),       u01=make_float2(-cl*s,-sl*s);
        float2 u10=make_float2(cp*s,sp*s),   u11=make_float2(cpl*c,spl*c);
        if (d.type==0) { M[0]=u00; M[1]=u01; M[2]=u10; M[3]=u11; }
        else { // CU3: [[I,0],[0,U]], control = first (a) index
            M[0]=make_float2(1.f,0.f); M[5]=make_float2(1.f,0.f);
            M[10]=u00; M[11]=u01; M[14]=u10; M[15]=u11;
        }
    } else if (d.type<=3) { // ising exp(-i phi/2 P)
        float phi=src[d.off]; float s,c; sincosf(0.5f*phi,&s,&c);
        if (d.type==1) { // ZZ: diag(c-is, c+is, c+is, c-is)
            M[0]=make_float2(c,-s); M[5]=make_float2(c,s);
            M[10]=make_float2(c,s); M[15]=make_float2(c,-s);
        } else {
            M[0]=M[5]=M[10]=M[15]=make_float2(c,0.f);
            if (d.type==3) { // XX: antidiag -is
                M[3]=M[6]=M[9]=M[12]=make_float2(0.f,-s);
            } else {         // YY: antidiag +is,-is,-is,+is
                M[3]=make_float2(0.f,s);  M[6]=make_float2(0.f,-s);
                M[9]=make_float2(0.f,-s); M[12]=make_float2(0.f,s);
            }
        }
    } else { // ARB: c*I - i s * (P_w0 kron P_w1)
        float th=src[d.off]; float s,c; sincosf(0.5f*th,&s,&c);
        #pragma unroll
        for (int i=0;i<4;i++)
          #pragma unroll
          for (int j=0;j<4;j++){
            float2 pa = PT[d.w0][(i>>1)*2+(j>>1)];
            float2 pb = PT[d.w1][(i&1)*2+(j&1)];
            float2 K  = cm(pa,pb);
            float2 v  = make_float2(s*K.y, -s*K.x); // (-i s)*K
            if (i==j) v.x += c;
            M[i*4+j]=v;
        }
    }
    #pragma unroll
    for (int i=0;i<16;i++) d_G[g*16+i]=M[i];
}

// ---------------- 2. evolve 256 basis columns -> U ----------------
// 64 CTAs x 256 threads; 4 columns per CTA (64 threads per column)
__global__ void __launch_bounds__(256) k_build() {
    __shared__ float2 sp[4][256];
    int tid=threadIdx.x, sub=tid>>6, t=tid&63;
    int col = blockIdx.x*4 + sub;
    float2* p = sp[sub];
    for (int k=t;k<256;k+=64) p[k]=make_float2(k==col?1.f:0.f, 0.f);
    __syncthreads();

    for (int g=0; g<66; g++) {
        GateDesc d = g_desc[g];
        const float2* G = d_G + g*16;
        if (d.type==0) { // 1q on wire a
            float2 g0=G[0],g1=G[1],g2=G[2],g3=G[3];
            int pos=7-d.a, mask=1<<pos;
            #pragma unroll
            for (int q=t;q<128;q+=64) {
                int k0 = ((q>>pos)<<(pos+1)) | (q & (mask-1));
                float2 a0=p[k0], a1=p[k0|mask];
                p[k0]      = ca(cm(g0,a0), cm(g1,a1));
                p[k0|mask] = ca(cm(g2,a0), cm(g3,a1));
            }
        } else { // generic 4x4 on (a,b), index i = 2*bit_a + bit_b
            int pa=7-d.a, pb=7-d.b;
            int p1 = pa<pb?pa:pb, p2 = pa<pb?pb:pa;
            int ma=1<<pa, mb=1<<pb;
            int low = t & ((1<<p1)-1);
            int mid = ((t >> p1) & ((1<<(p2-1-p1))-1)) << (p1+1);
            int hi  = (t >> (p2-1)) << (p2+1);
            int k0 = hi|mid|low;
            float2 v0=p[k0], v1=p[k0|mb], v2=p[k0|ma], v3=p[k0|ma|mb];
            float2 r0 = ca(ca(cm(G[0],v0), cm(G[1],v1)), ca(cm(G[2],v2), cm(G[3],v3)));
            float2 r1 = ca(ca(cm(G[4],v0), cm(G[5],v1)), ca(cm(G[6],v2), cm(G[7],v3)));
            float2 r2 = ca(ca(cm(G[8],v0), cm(G[9],v1)), ca(cm(G[10],v2),cm(G[11],v3)));
            float2 r3 = ca(ca(cm(G[12],v0),cm(G[13],v1)), ca(cm(G[14],v2),cm(G[15],v3)));
            p[k0]=r0; p[k0|mb]=r1; p[k0|ma]=r2; p[k0|ma|mb]=r3;
        }
        __syncthreads();
    }
    for (int k=t;k<256;k+=64) d_U[k*256+col]=p[k];
}

// ---------------- 3. A = Re(U^dag S U), S = Z on qubit0 (bit7) ----------------
// 16 blocks x 256 threads; block handles 16 i-rows, thread = column j
__global__ void __launch_bounds__(256) k_M() {
    __shared__ float2 su[16][256];
    int tid = threadIdx.x;
    int i0 = blockIdx.x*16;
    for (int idx=tid; idx<16*256; idx+=256) {
        int ii = idx>>8, k = idx&255;
        float2 u = d_U[k*256 + i0 + ii];
        float sgn = (k & 128) ? -1.f : 1.f;
        su[ii][k] = make_float2(u.x*sgn, u.y*sgn);
    }
    __syncthreads();
    int j = tid;
    float acc[16];
    #pragma unroll
    for (int ii=0;ii<16;ii++) acc[ii]=0.f;
    for (int k=0;k<256;k++){
        float2 b = d_U[k*256+j];
        #pragma unroll
        for (int ii=0;ii<16;ii++){
            float2 a = su[ii][k];
            acc[ii] += a.x*b.x + a.y*b.y;  // Re(conj(a)*b)
        }
    }
    #pragma unroll
    for (int ii=0;ii<16;ii++) d_M[(i0+ii)*256 + j] = acc[ii];
}

// ---------------- 4. Pauli coefficients m_p = Tr[A P]/256 ----------------
// word index c = sum_w p_w * 3^(7-w), p: 0=I,1=X,2=Z
__global__ void k_coeff() {
    int c = blockIdx.x*256 + threadIdx.x;
    if (c >= 6561) return;
    int xm=0, zm=0, cc=c;
    #pragma unroll
    for (int w=7; w>=0; w--) {
        int d = cc % 3; cc /= 3;
        if (d==1) xm |= 1<<(7-w);
        else if (d==2) zm |= 1<<(7-w);
    }
    float s = 0.f;
    #pragma unroll 8
    for (int i=0;i<256;i++){
        float v = d_M[(i^xm)*256 + i];
        s += (__popc(i & zm) & 1) ? -v : v;
    }
    ((float*)d_mpad)[(c/3)*4 + (c%3)] = s * (1.f/256.f);
}

// ---------------- 5. GEMM + tanh: reduced = tanh(x @ W^T + b) ----------------
// 256 CTAs x 512 threads; CTA = 64 rows, warp = 4 rows; W staged in 48KB smem in 2 K-halves
__global__ void __launch_bounds__(512) k_gemm(const float* __restrict__ x,
                                              const float* __restrict__ w,
                                              const float* __restrict__ b) {
    __shared__ float4 sw4[3072]; // 8 x 1536 floats = 48KB
    int tid = threadIdx.x;
    int warp = tid>>5, lane = tid&31;
    int row0 = blockIdx.x*64 + warp*4;
    const float4* w4g = (const float4*)w;

    float acc[4][8];
    #pragma unroll
    for (int r=0;r<4;r++)
      #pragma unroll
      for (int j=0;j<8;j++) acc[r][j]=0.f;

    for (int h=0; h<2; h++) {
        __syncthreads();
        for (int i=tid; i<3072; i+=512) {
            int j = i/384, kk4 = i%384;                 // 384 float4 per (row, half)
            sw4[j*384 + kk4] = w4g[j*768 + h*384 + kk4];
        }
        __syncthreads();
        #pragma unroll 2
        for (int c=0; c<12; c++) {
            int kk = c*128 + lane*4;
            float4 xv[4];
            #pragma unroll
            for (int r=0;r<4;r++)
                xv[r] = *(const float4*)&x[(row0+r)*KDIM + h*1536 + kk];
            #pragma unroll
            for (int j=0;j<8;j++){
                float4 wv = sw4[j*384 + c*32 + lane];
                #pragma unroll
                for (int r=0;r<4;r++)
                    acc[r][j] += xv[r].x*wv.x + xv[r].y*wv.y + xv[r].z*wv.z + xv[r].w*wv.w;
            }
        }
    }
    // warp reduction
    #pragma unroll
    for (int r=0;r<4;r++)
      #pragma unroll
      for (int j=0;j<8;j++)
        #pragma unroll
        for (int o=16;o;o>>=1)
            acc[r][j] += __shfl_xor_sync(0xffffffffu, acc[r][j], o);
    if (lane==0) {
        #pragma unroll
        for (int r=0;r<4;r++)
          #pragma unroll
          for (int j=0;j<8;j++)
            d_red[(row0+r)*8 + j] = tanhf(acc[r][j] + b[j]);
    }
}

// ---------------- 6. contraction: z0 = sum_p m_p * prod f ----------------
// grid (64, 3): blockIdx.y = slice = p_0 digit; 729 float4 groups per slice
__global__ void __launch_bounds__(256) k_contract() {
    __shared__ float4 sm[729];
    int tid = threadIdx.x;
    int s = blockIdx.y;
    for (int i=tid;i<729;i+=256) sm[i] = d_mpad[s*729 + i];
    __syncthreads();

    int bidx = blockIdx.x*256 + tid;
    float g[8][3];
    #pragma unroll
    for (int w=0;w<8;w++){
        float th = d_red[bidx*8 + w];
        float sn, cs; sincosf(th,&sn,&cs);
        g[w][0]=1.f; g[w][1]=sn; g[w][2]=cs;
    }
    float s7=g[7][1], c7=g[7][2];
    float z=0.f; int idx=0;
    #pragma unroll 1
    for (int i1=0;i1<3;i1++){ float p1=g[1][i1];
      #pragma unroll 1
      for (int i2=0;i2<3;i2++){ float p2=p1*g[2][i2];
        #pragma unroll 1
        for (int i3=0;i3<3;i3++){ float p3=p2*g[3][i3];
          #pragma unroll 1
          for (int i4=0;i4<3;i4++){ float p4=p3*g[4][i4];
            #pragma unroll
            for (int i5=0;i5<3;i5++){ float p5=p4*g[5][i5];
              #pragma unroll
              for (int i6=0;i6<3;i6++){ float p6=p5*g[6][i6];
                float4 m = sm[idx++];
                z += p6*(m.x + m.y*s7 + m.z*c7);
              }
            }
          }
        }
      }
    }
    d_part[s*B_ + bidx] = z * g[0][s];
}

// ---------------- 7. logits ----------------
__global__ void k_logits(const float* __restrict__ ow, const float* __restrict__ ob,
                         float* __restrict__ out) {
    int bidx = blockIdx.x*256 + threadIdx.x;
    float z = d_part[bidx] + d_part[B_+bidx] + d_part[2*B_+bidx];
    #pragma unroll
    for (int c=0;c<10;c++) out[bidx*10 + c] = z*ow[c] + ob[c];
}

// ---------------- launch ----------------
extern "C" void kernel_launch(void* const* d_in, const int* in_sizes, int n_in,
                              void* d_out, int out_size) {
    const float* x    = (const float*)d_in[0];
    const float* fw   = (const float*)d_in[1];
    const float* fb   = (const float*)d_in[2];
    const float* conv = (const float*)d_in[3];
    const float* pool = (const float*)d_in[4];
    const float* last = (const float*)d_in[5];
    const float* ow   = (const float*)d_in[6];
    const float* ob   = (const float*)d_in[7];
    float* out = (float*)d_out;

    k_gates<<<1,128>>>(conv, pool, last);
    k_build<<<64,256>>>();
    k_M<<<16,256>>>();
    k_coeff<<<26,256>>>();
    k_gemm<<<256,512>>>(x, fw, fb);
    dim3 gc(64,3);
    k_contract<<<gc,256>>>();
    k_logits<<<64,256>>>(ow, ob, out);
}

// round 2
// speedup vs baseline: 1.5629x; 1.5629x over previous
#include <cuda_runtime.h>
#include <math.h>

#define B_   16384
#define KDIM 3072

// ---------------- gate descriptor table ----------------
// type: 0=U3(wire a), 1=ZZ(a,b), 2=YY, 3=XX, 4=CU3(ctrl=a,tgt=b), 5=ARB(pauli w0 on a, w1 on b)
typedef struct { int type, a, b, src, off, w0, w1; } GateDesc;

__constant__ GateDesc g_desc[66] = {
  {0,0,0,0,0,0,0},{0,2,0,0,33,0,0},{1,0,2,0,6,0,0},{2,0,2,0,7,0,0},{3,0,2,0,8,0,0},{0,0,0,0,9,0,0},{0,2,0,0,42,0,0},
  {0,1,0,0,15,0,0},{0,3,0,0,48,0,0},{1,1,3,0,21,0,0},{2,1,3,0,22,0,0},{3,1,3,0,23,0,0},{0,1,0,0,24,0,0},{0,3,0,0,57,0,0},
  {0,4,0,0,60,0,0},{0,6,0,0,93,0,0},{1,4,6,0,66,0,0},{2,4,6,0,67,0,0},{3,4,6,0,68,0,0},{0,4,0,0,69,0,0},{0,6,0,0,102,0,0},
  {0,5,0,0,75,0,0},{0,7,0,0,108,0,0},{1,5,7,0,81,0,0},{2,5,7,0,82,0,0},{3,5,7,0,83,0,0},{0,5,0,0,84,0,0},{0,7,0,0,117,0,0},
  {4,1,0,1,0,0,0},{4,3,2,1,3,0,0},{4,5,4,1,6,0,0},{4,7,6,1,9,0,0},
  {0,0,0,0,120,0,0},{0,2,0,0,153,0,0},{1,0,2,0,126,0,0},{2,0,2,0,127,0,0},{3,0,2,0,128,0,0},{0,0,0,0,129,0,0},{0,2,0,0,162,0,0},
  {0,4,0,0,180,0,0},{0,4,0,0,183,0,0},{0,4,0,0,186,0,0},{0,4,0,0,189,0,0},{0,4,0,0,192,0,0},
  {0,6,0,0,210,0,0},{0,6,0,0,213,0,0},{0,6,0,0,216,0,0},{0,6,0,0,219,0,0},{0,6,0,0,222,0,0},
  {4,2,0,1,12,0,0},{4,6,4,1,15,0,0},
  {5,0,4,2,0,1,0},{5,0,4,2,1,2,0},{5,0,4,2,2,3,0},{5,0,4,2,3,3,1},{5,0,4,2,4,0,1},
  {5,0,4,2,5,1,1},{5,0,4,2,6,2,1},{5,0,4,2,7,2,2},{5,0,4,2,8,3,2},{5,0,4,2,9,0,2},
  {5,0,4,2,10,1,2},{5,0,4,2,11,1,3},{5,0,4,2,12,2,3},{5,0,4,2,13,3,3},{5,0,4,2,14,0,3}
};

__constant__ float2 PT[4][4] = {
  {{1.f,0.f},{0.f,0.f},{0.f,0.f},{1.f,0.f}},
  {{0.f,0.f},{1.f,0.f},{1.f,0.f},{0.f,0.f}},
  {{0.f,0.f},{0.f,-1.f},{0.f,1.f},{0.f,0.f}},
  {{1.f,0.f},{0.f,0.f},{0.f,0.f},{-1.f,0.f}}
};

// ---------------- device scratch ----------------
__device__ float2 d_U[256*256];    // U[k*256 + col]
__device__ float  d_M[256*256];    // A = Re(U^dag Z0 U)
__device__ float4 d_mpad[2187];    // 6561 Pauli coeffs, groups of 3 padded to float4
__device__ float2 d_trig[B_*8];    // (sin,cos) of tanh(x@W^T+b)
__device__ float  d_part[9*B_];    // partial contractions per slice

__device__ __forceinline__ float2 cm(float2 a, float2 b){
    return make_float2(a.x*b.x - a.y*b.y, a.x*b.y + a.y*b.x);
}
__device__ __forceinline__ float2 ca(float2 a, float2 b){
    return make_float2(a.x+b.x, a.y+b.y);
}
__device__ __forceinline__ void ffma2(unsigned long long &acc, unsigned long long a, unsigned long long b){
    asm("fma.rn.f32x2 %0, %1, %2, %0;" : "+l"(acc) : "l"(a), "l"(b));
}

// ---------------- gate construction (device fn) ----------------
__device__ void make_gate(int g, const float* conv, const float* pool,
                          const float* last, float2* out) {
    GateDesc d = g_desc[g];
    const float* src = (d.src==0) ? conv : ((d.src==1) ? pool : last);
    float2 M[16];
    #pragma unroll
    for (int i=0;i<16;i++) M[i]=make_float2(0.f,0.f);

    if (d.type==0 || d.type==4) {
        float th=src[d.off], ph=src[d.off+1], lam=src[d.off+2];
        float s,c;   sincosf(0.5f*th,&s,&c);
        float sl,cl; sincosf(lam,&sl,&cl);
        float sp,cp; sincosf(ph,&sp,&cp);
        float spl,cpl; sincosf(ph+lam,&spl,&cpl);
        float2 u00=make_float2(c,0.f),       u01=make_float2(-cl*s,-sl*s);
        float2 u10=make_float2(cp*s,sp*s),   u11=make_float2(cpl*c,spl*c);
        if (d.type==0) { M[0]=u00; M[1]=u01; M[2]=u10; M[3]=u11; }
        else {
            M[0]=make_float2(1.f,0.f); M[5]=make_float2(1.f,0.f);
            M[10]=u00; M[11]=u01; M[14]=u10; M[15]=u11;
        }
    } else if (d.type<=3) {
        float phi=src[d.off]; float s,c; sincosf(0.5f*phi,&s,&c);
        if (d.type==1) {
            M[0]=make_float2(c,-s); M[5]=make_float2(c,s);
            M[10]=make_float2(c,s); M[15]=make_float2(c,-s);
        } else {
            M[0]=M[5]=M[10]=M[15]=make_float2(c,0.f);
            if (d.type==3) {
                M[3]=M[6]=M[9]=M[12]=make_float2(0.f,-s);
            } else {
                M[3]=make_float2(0.f,s);  M[6]=make_float2(0.f,-s);
                M[9]=make_float2(0.f,-s); M[12]=make_float2(0.f,s);
            }
        }
    } else {
        float th=src[d.off]; float s,c; sincosf(0.5f*th,&s,&c);
        #pragma unroll
        for (int i=0;i<4;i++)
          #pragma unroll
          for (int j=0;j<4;j++){
            float2 pa = PT[d.w0][(i>>1)*2+(j>>1)];
            float2 pb = PT[d.w1][(i&1)*2+(j&1)];
            float2 K  = cm(pa,pb);
            float2 v  = make_float2(s*K.y, -s*K.x);
            if (i==j) v.x += c;
            M[i*4+j]=v;
        }
    }
    #pragma unroll
    for (int i=0;i<16;i++) out[i]=M[i];
}

// ---------------- 1. build gates (in smem) + evolve 256 basis cols -> U ----------------
__global__ void __launch_bounds__(256) k_build(const float* __restrict__ conv,
                                               const float* __restrict__ pool,
                                               const float* __restrict__ last) {
    __shared__ float2 sG[66*16];
    __shared__ float2 sp[4][256];
    int tid=threadIdx.x, sub=tid>>6, t=tid&63;
    if (tid < 66) make_gate(tid, conv, pool, last, &sG[tid*16]);
    int col = blockIdx.x*4 + sub;
    float2* p = sp[sub];
    for (int k=t;k<256;k+=64) p[k]=make_float2(k==col?1.f:0.f, 0.f);
    __syncthreads();

    for (int g=0; g<66; g++) {
        GateDesc d = g_desc[g];
        const float2* G = sG + g*16;
        if (d.type==0) {
            float2 g0=G[0],g1=G[1],g2=G[2],g3=G[3];
            int pos=7-d.a, mask=1<<pos;
            #pragma unroll
            for (int q=t;q<128;q+=64) {
                int k0 = ((q>>pos)<<(pos+1)) | (q & (mask-1));
                float2 a0=p[k0], a1=p[k0|mask];
                p[k0]      = ca(cm(g0,a0), cm(g1,a1));
                p[k0|mask] = ca(cm(g2,a0), cm(g3,a1));
            }
        } else {
            int pa=7-d.a, pb=7-d.b;
            int p1 = pa<pb?pa:pb, p2 = pa<pb?pb:pa;
            int ma=1<<pa, mb=1<<pb;
            int low = t & ((1<<p1)-1);
            int mid = ((t >> p1) & ((1<<(p2-1-p1))-1)) << (p1+1);
            int hi  = (t >> (p2-1)) << (p2+1);
            int k0 = hi|mid|low;
            float2 v0=p[k0], v1=p[k0|mb], v2=p[k0|ma], v3=p[k0|ma|mb];
            float2 r0 = ca(ca(cm(G[0],v0), cm(G[1],v1)), ca(cm(G[2],v2), cm(G[3],v3)));
            float2 r1 = ca(ca(cm(G[4],v0), cm(G[5],v1)), ca(cm(G[6],v2), cm(G[7],v3)));
            float2 r2 = ca(ca(cm(G[8],v0), cm(G[9],v1)), ca(cm(G[10],v2),cm(G[11],v3)));
            float2 r3 = ca(ca(cm(G[12],v0),cm(G[13],v1)), ca(cm(G[14],v2),cm(G[15],v3)));
            p[k0]=r0; p[k0|mb]=r1; p[k0|ma]=r2; p[k0|ma|mb]=r3;
        }
        __syncthreads();
    }
    for (int k=t;k<256;k+=64) d_U[k*256+col]=p[k];
}

// ---------------- 2. A = Re(U^dag S U), S = Z on bit7 ----------------
// 64 blocks x 256 threads; block = 4 i-rows, thread = column j
__global__ void __launch_bounds__(256) k_M() {
    __shared__ float2 su[4][256];
    int tid = threadIdx.x;
    int i0 = blockIdx.x*4;
    for (int idx=tid; idx<4*256; idx+=256) {
        int ii = idx>>8, k = idx&255;
        float2 u = d_U[k*256 + i0 + ii];
        float sgn = (k & 128) ? -1.f : 1.f;
        su[ii][k] = make_float2(u.x*sgn, u.y*sgn);
    }
    __syncthreads();
    int j = tid;
    unsigned long long acc[4] = {0ull,0ull,0ull,0ull};
    const unsigned long long* ub = (const unsigned long long*)d_U;
    #pragma unroll 8
    for (int k=0;k<256;k++){
        unsigned long long b = ub[k*256+j];
        #pragma unroll
        for (int ii=0;ii<4;ii++){
            unsigned long long a = *(const unsigned long long*)&su[ii][k];
            ffma2(acc[ii], a, b);   // packed: (ax*bx, ay*by) accumulate
        }
    }
    #pragma unroll
    for (int ii=0;ii<4;ii++){
        float2 v = *(float2*)&acc[ii];
        d_M[(i0+ii)*256 + j] = v.x + v.y;   // Re(conj(a)*b)
    }
}

// ---------------- 3. Pauli coefficients: 8 threads per word ----------------
__global__ void __launch_bounds__(256) k_coeff() {
    int gid = blockIdx.x*256 + threadIdx.x;
    int word = gid >> 3, r = gid & 7;
    if (word >= 6561) return;
    int xm=0, zm=0, cc=word;
    #pragma unroll
    for (int w=0; w<8; w++) {
        int d = cc % 3; cc /= 3;
        if (d==1) xm |= 1<<w;
        else if (d==2) zm |= 1<<w;
    }
    float s = 0.f;
    int ibase = r*32;
    #pragma unroll
    for (int q=0;q<32;q++){
        int i = ibase + q;
        float v = d_M[(i^xm)*256 + i];
        s += (__popc(i & zm) & 1) ? -v : v;
    }
    #pragma unroll
    for (int o=4;o;o>>=1) s += __shfl_down_sync(0xffffffffu, s, o, 8);
    if (r==0)
        ((float*)d_mpad)[(word/3)*4 + (word%3)] = s * (1.f/256.f);
}

// ---------------- 4. GEMM + tanh + sincos ----------------
// 256 CTAs x 512 threads; CTA = 64 rows, warp = 4 rows; W staged in 48KB smem, 2 K-halves
__global__ void __launch_bounds__(512) k_gemm(const float* __restrict__ x,
                                              const float* __restrict__ w,
                                              const float* __restrict__ b) {
    __shared__ float4 sw4[3072]; // 48KB
    int tid = threadIdx.x;
    int warp = tid>>5, lane = tid&31;
    int row0 = blockIdx.x*64 + warp*4;
    const float4* w4g = (const float4*)w;

    unsigned long long acc[4][8];
    #pragma unroll
    for (int r=0;r<4;r++)
      #pragma unroll
      for (int j=0;j<8;j++) acc[r][j]=0ull;

    for (int h=0; h<2; h++) {
        __syncthreads();
        for (int i=tid; i<3072; i+=512) {
            int j = i/384, kk4 = i%384;
            sw4[j*384 + kk4] = w4g[j*768 + h*384 + kk4];
        }
        __syncthreads();
        #pragma unroll 2
        for (int c=0; c<12; c++) {
            int kk = c*128 + lane*4;
            unsigned long long xl[4], xh[4];
            #pragma unroll
            for (int r=0;r<4;r++){
                float4 xv = *(const float4*)&x[(row0+r)*KDIM + h*1536 + kk];
                xl[r] = *(unsigned long long*)&xv.x;
                xh[r] = *(unsigned long long*)&xv.z;
            }
            #pragma unroll
            for (int j=0;j<8;j++){
                float4 wv = sw4[j*384 + c*32 + lane];
                unsigned long long wl = *(unsigned long long*)&wv.x;
                unsigned long long wh = *(unsigned long long*)&wv.z;
                #pragma unroll
                for (int r=0;r<4;r++){
                    ffma2(acc[r][j], xl[r], wl);
                    ffma2(acc[r][j], xh[r], wh);
                }
            }
        }
    }
    #pragma unroll
    for (int r=0;r<4;r++)
      #pragma unroll
      for (int j=0;j<8;j++){
        float2 v = *(float2*)&acc[r][j];
        float a = v.x + v.y;
        #pragma unroll
        for (int o=16;o;o>>=1)
            a += __shfl_xor_sync(0xffffffffu, a, o);
        if (lane==0){
            float th = tanhf(a + b[j]);
            float sn, cs; sincosf(th,&sn,&cs);
            d_trig[(row0+r)*8 + j] = make_float2(sn,cs);
        }
      }
}

// ---------------- 5. contraction, 9 slices (p0,p1) ----------------
__global__ void __launch_bounds__(256) k_contract() {
    __shared__ float4 sm[243];
    int tid = threadIdx.x;
    int s01 = blockIdx.y;
    if (tid < 243) sm[tid] = d_mpad[s01*243 + tid];
    __syncthreads();

    int bidx = blockIdx.x*256 + tid;
    float2 tg[8];
    #pragma unroll
    for (int w=0;w<8;w++) tg[w] = d_trig[bidx*8 + w];

    float g2[3]={1.f,tg[2].x,tg[2].y}, g3[3]={1.f,tg[3].x,tg[3].y};
    float g4[3]={1.f,tg[4].x,tg[4].y}, g5[3]={1.f,tg[5].x,tg[5].y};
    float g6[3]={1.f,tg[6].x,tg[6].y};
    float s7=tg[7].x, c7=tg[7].y;

    float z=0.f; int idx=0;
    #pragma unroll 1
    for (int i2=0;i2<3;i2++){ float p2=g2[i2];
      #pragma unroll 1
      for (int i3=0;i3<3;i3++){ float p3=p2*g3[i3];
        #pragma unroll 1
        for (int i4=0;i4<3;i4++){ float p4=p3*g4[i4];
          #pragma unroll
          for (int i5=0;i5<3;i5++){ float p5=p4*g5[i5];
            #pragma unroll
            for (int i6=0;i6<3;i6++){ float p6=p5*g6[i6];
              float4 m = sm[idx++];
              z += p6*(m.x + m.y*s7 + m.z*c7);
            }
          }
        }
      }
    }
    int s0=s01/3, s1=s01%3;
    float f0 = (s0==0)?1.f:((s0==1)?tg[0].x:tg[0].y);
    float f1 = (s1==0)?1.f:((s1==1)?tg[1].x:tg[1].y);
    d_part[s01*B_ + bidx] = z * f0 * f1;
}

// ---------------- 6. logits ----------------
__global__ void __launch_bounds__(256) k_logits(const float* __restrict__ ow,
                                                const float* __restrict__ ob,
                                                float* __restrict__ out) {
    int bidx = blockIdx.x*256 + threadIdx.x;
    float z = 0.f;
    #pragma unroll
    for (int s=0;s<9;s++) z += d_part[s*B_ + bidx];
    #pragma unroll
    for (int c=0;c<10;c++) out[bidx*10 + c] = z*ow[c] + ob[c];
}

// ---------------- launch ----------------
extern "C" void kernel_launch(void* const* d_in, const int* in_sizes, int n_in,
                              void* d_out, int out_size) {
    const float* x    = (const float*)d_in[0];
    const float* fw   = (const float*)d_in[1];
    const float* fb   = (const float*)d_in[2];
    const float* conv = (const float*)d_in[3];
    const float* pool = (const float*)d_in[4];
    const float* last = (const float*)d_in[5];
    const float* ow   = (const float*)d_in[6];
    const float* ob   = (const float*)d_in[7];
    float* out = (float*)d_out;

    k_gemm<<<256,512>>>(x, fw, fb);
    k_build<<<64,256>>>(conv, pool, last);
    k_M<<<64,256>>>();
    k_coeff<<<206,256>>>();
    dim3 gc(64,9);
    k_contract<<<gc,256>>>();
    k_logits<<<64,256>>>(ow, ob, out);
}